// round 2
// baseline (speedup 1.0000x reference)
#include <cuda_runtime.h>
#include <math.h>

// GeometricFeatureExtractor: coords (N,3) f32 -> angles (N,3) + frames (N,3,3)
// Output layout assumed: [angles (3N floats)][frames (9N floats)] per reference
// tuple order.

__global__ void geo_kernel(const float* __restrict__ coords,
                           float* __restrict__ angles,
                           float* __restrict__ frames,
                           int n)
{
    int i = blockIdx.x * blockDim.x + threadIdx.x;
    if (i >= n) return;

    // Frame for row 0 copies row 1; row n-1 copies row n-2. Clamp the stencil
    // center so edge threads recompute the neighbor's frame directly.
    int c = i;
    if (c < 1) c = 1;
    if (c > n - 2) c = n - 2;

    const float* p = coords + 3 * (c - 1);
    float ax = p[0], ay = p[1], az = p[2];
    float bx = p[3], by = p[4], bz = p[5];
    float cx = p[6], cy = p[7], cz = p[8];

    // consecutive differences
    float d1x = bx - ax, d1y = by - ay, d1z = bz - az;
    float d2x = cx - bx, d2y = cy - by, d2z = cz - bz;

    // normalize: v / (||v|| + 1e-10)
    float n1 = sqrtf(d1x * d1x + d1y * d1y + d1z * d1z) + 1e-10f;
    float r1 = 1.0f / n1;
    float v1x = d1x * r1, v1y = d1y * r1, v1z = d1z * r1;

    float n2 = sqrtf(d2x * d2x + d2y * d2y + d2z * d2z) + 1e-10f;
    float r2 = 1.0f / n2;
    float v2x = d2x * r2, v2y = d2y * r2, v2z = d2z * r2;

    // torsion angle
    float dot = v1x * v2x + v1y * v2y + v1z * v2z;
    float cosang = fminf(1.0f, fmaxf(-1.0f, dot));
    float ang = acosf(cosang);

    // Gram-Schmidt: e2 = normalize(v2 - (v2.e1) e1)  (proj uses unclipped dot)
    float ux = v2x - dot * v1x;
    float uy = v2y - dot * v1y;
    float uz = v2z - dot * v1z;
    float nu = sqrtf(ux * ux + uy * uy + uz * uz) + 1e-10f;
    float ru = 1.0f / nu;
    float e2x = ux * ru, e2y = uy * ru, e2z = uz * ru;

    // e3 = e1 x e2
    float e3x = v1y * e2z - v1z * e2y;
    float e3y = v1z * e2x - v1x * e2z;
    float e3z = v1x * e2y - v1y * e2x;

    // angles: zero on edge rows, replicated x3 otherwise
    float a = (i == 0 || i == n - 1) ? 0.0f : ang;
    float* arow = angles + 3 * (size_t)i;
    arow[0] = a; arow[1] = a; arow[2] = a;

    // frames: rows e1, e2, e3 (row-major 3x3)
    float* f = frames + 9 * (size_t)i;
    f[0] = v1x; f[1] = v1y; f[2] = v1z;
    f[3] = e2x; f[4] = e2y; f[5] = e2z;
    f[6] = e3x; f[7] = e3y; f[8] = e3z;
}

extern "C" void kernel_launch(void* const* d_in, const int* in_sizes, int n_in,
                              void* d_out, int out_size)
{
    const float* coords = (const float*)d_in[0];
    int n = in_sizes[0] / 3;

    float* angles = (float*)d_out;            // (N,3)
    float* frames = (float*)d_out + 3 * (size_t)n; // (N,3,3)

    int threads = 256;
    int blocks = (n + threads - 1) / threads;
    geo_kernel<<<blocks, threads>>>(coords, angles, frames, n);
}

// round 5
// speedup vs baseline: 2.2995x; 2.2995x over previous
#include <cuda_runtime.h>
#include <math.h>
#include <stdint.h>

// GeometricFeatureExtractor: coords (N,3) f32 -> angles (N,3) + frames (N,3,3)
// Output layout: [angles (3N floats)][frames (9N floats)].
//
// Shared-memory staged, vectorized: coalesced scalar loads of the halo'd coord
// tile, per-thread compute out of shared, float4 stores of both output regions.
// Shared arrays are 16B-aligned (required for LDS.128); global vector path is
// guarded by a runtime alignment check.

#define TILE 256

__global__ __launch_bounds__(TILE) void geo_kernel(
    const float* __restrict__ coords,
    float* __restrict__ angles,
    float* __restrict__ frames,
    int n)
{
    __shared__ alignas(16) float s_c[(TILE + 2) * 3];  // rows [base-1, base+TILE]
    __shared__ alignas(16) float s_ang[TILE];
    __shared__ alignas(16) float s_fr[TILE * 9];

    const int base = blockIdx.x * TILE;
    const int tid  = threadIdx.x;

    // ---- Phase 1: cooperative coalesced load of coord tile + halo ----
    for (int idx = tid; idx < (TILE + 2) * 3; idx += TILE) {
        int row  = idx / 3;
        int comp = idx - row * 3;
        int g = base - 1 + row;
        g = min(max(g, 0), n - 1);
        s_c[idx] = coords[3 * (size_t)g + comp];
    }
    __syncthreads();

    // ---- Phase 2: per-thread compute into shared ----
    const int i = base + tid;
    if (i < n) {
        int c = min(max(i, 1), n - 2);          // edge rows recompute neighbor frame
        const float* p = s_c + 3 * (c - base);  // local index of row c-1

        float ax = p[0], ay = p[1], az = p[2];
        float bx = p[3], by = p[4], bz = p[5];
        float cx = p[6], cy = p[7], cz = p[8];

        float d1x = bx - ax, d1y = by - ay, d1z = bz - az;
        float d2x = cx - bx, d2y = cy - by, d2z = cz - bz;

        float n1 = sqrtf(d1x * d1x + d1y * d1y + d1z * d1z) + 1e-10f;
        float r1 = 1.0f / n1;
        float v1x = d1x * r1, v1y = d1y * r1, v1z = d1z * r1;

        float n2 = sqrtf(d2x * d2x + d2y * d2y + d2z * d2z) + 1e-10f;
        float r2 = 1.0f / n2;
        float v2x = d2x * r2, v2y = d2y * r2, v2z = d2z * r2;

        float dot = v1x * v2x + v1y * v2y + v1z * v2z;
        float cosang = fminf(1.0f, fmaxf(-1.0f, dot));
        float ang = acosf(cosang);

        float ux = v2x - dot * v1x;
        float uy = v2y - dot * v1y;
        float uz = v2z - dot * v1z;
        float nu = sqrtf(ux * ux + uy * uy + uz * uz) + 1e-10f;
        float ru = 1.0f / nu;
        float e2x = ux * ru, e2y = uy * ru, e2z = uz * ru;

        float e3x = v1y * e2z - v1z * e2y;
        float e3y = v1z * e2x - v1x * e2z;
        float e3z = v1x * e2y - v1y * e2x;

        s_ang[tid] = (i == 0 || i == n - 1) ? 0.0f : ang;

        float* f = s_fr + 9 * tid;
        f[0] = v1x; f[1] = v1y; f[2] = v1z;
        f[3] = e2x; f[4] = e2y; f[5] = e2z;
        f[6] = e3x; f[7] = e3y; f[8] = e3z;
    }
    __syncthreads();

    // ---- Phase 3: vectorized store ----
    const int count = min(TILE, n - base);
    float* aptr = angles + 3 * (size_t)base;
    float* fptr = frames + 9 * (size_t)base;
    bool aligned16 = ((((uintptr_t)aptr) | ((uintptr_t)fptr)) & 15u) == 0;

    if (count == TILE && aligned16) {
        // angles: TILE*3 = 768 floats = 192 float4
        float4* aout = (float4*)aptr;
        if (tid < (TILE * 3) / 4) {
            int j = 4 * tid;
            float4 v;
            v.x = s_ang[(j + 0) / 3];
            v.y = s_ang[(j + 1) / 3];
            v.z = s_ang[(j + 2) / 3];
            v.w = s_ang[(j + 3) / 3];
            aout[tid] = v;
        }
        // frames: TILE*9 = 2304 floats = 576 float4
        float4* fout = (float4*)fptr;
        const float4* sf = (const float4*)s_fr;
        #pragma unroll
        for (int k = 0; k < 3; ++k) {            // 3*256 = 768 > 576, guard below
            int idx = tid + k * TILE;
            if (idx < (TILE * 9) / 4) fout[idx] = sf[idx];
        }
    } else {
        // partial last tile or unaligned: scalar fallback
        for (int idx = tid; idx < count * 3; idx += TILE)
            aptr[idx] = s_ang[idx / 3];
        for (int idx = tid; idx < count * 9; idx += TILE)
            fptr[idx] = s_fr[idx];
    }
}

extern "C" void kernel_launch(void* const* d_in, const int* in_sizes, int n_in,
                              void* d_out, int out_size)
{
    const float* coords = (const float*)d_in[0];
    int n = in_sizes[0] / 3;

    float* angles = (float*)d_out;                  // (N,3)
    float* frames = (float*)d_out + 3 * (size_t)n;  // (N,3,3)

    int blocks = (n + TILE - 1) / TILE;
    geo_kernel<<<blocks, TILE>>>(coords, angles, frames, n);
}

// round 7
// speedup vs baseline: 3.1581x; 1.3734x over previous
#include <cuda_runtime.h>
#include <math.h>
#include <stdint.h>

// GeometricFeatureExtractor: coords (N,3) f32 -> angles (N,3) + frames (N,3,3)
// Output layout: [angles (3N floats)][frames (9N floats)].
//
// TILE=512 rows per block, 256 threads x 2 rows. Interior blocks load the
// halo'd coord tile with float4 (from 16B-aligned offset 3*base-4), compute
// out of shared, and store both outputs as float4. Edge/partial blocks use
// scalar clamped fallbacks.

#define THREADS 256
#define ROWS_PER 2
#define TILE (THREADS * ROWS_PER)          // 512
#define SC_FLOATS (3 * TILE + 8)           // local offsets 0..1543 (row r at 3*(r-base)+4)

__global__ __launch_bounds__(THREADS) void geo_kernel(
    const float* __restrict__ coords,
    float* __restrict__ angles,
    float* __restrict__ frames,
    int n)
{
    __shared__ alignas(16) float s_c[SC_FLOATS];
    __shared__ alignas(16) float s_ang[TILE];
    __shared__ alignas(16) float s_fr[TILE * 9];

    const int base = blockIdx.x * TILE;
    const int tid  = threadIdx.x;

    // ---- Phase 1: load coord tile + halo into shared ----
    // Local layout: global row r lives at float offset 3*(r-base)+4.
    const bool interior = (base >= 1) && (base + TILE + 2 <= n);
    if (interior) {
        // gstart = 3*base - 4 is 16B-aligned (3*base divisible by 4 since TILE=512)
        const float4* gin = (const float4*)(coords + (3 * (size_t)base - 4));
        float4* sc4 = (float4*)s_c;
        #pragma unroll
        for (int k = 0; k < 2; ++k) {
            int v = tid + k * THREADS;
            if (v < SC_FLOATS / 4) sc4[v] = gin[v];
        }
    } else {
        for (int idx = tid; idx < (TILE + 2) * 3; idx += THREADS) {
            int row  = idx / 3;
            int comp = idx - row * 3;
            int g = base - 1 + row;
            g = min(max(g, 0), n - 1);
            s_c[3 * row + 1 + comp] = coords[3 * (size_t)g + comp];
        }
    }
    __syncthreads();

    // ---- Phase 2: per-thread compute (2 rows) into shared ----
    #pragma unroll
    for (int rr = 0; rr < ROWS_PER; ++rr) {
        const int lrow = tid + rr * THREADS;
        const int i = base + lrow;
        if (i < n) {
            int c = min(max(i, 1), n - 2);       // edge rows recompute neighbor frame
            const float* p = s_c + 3 * (c - base) + 1;  // row c-1

            float ax = p[0], ay = p[1], az = p[2];
            float bx = p[3], by = p[4], bz = p[5];
            float cx = p[6], cy = p[7], cz = p[8];

            float d1x = bx - ax, d1y = by - ay, d1z = bz - az;
            float d2x = cx - bx, d2y = cy - by, d2z = cz - bz;

            float n1 = sqrtf(d1x * d1x + d1y * d1y + d1z * d1z) + 1e-10f;
            float r1 = 1.0f / n1;
            float v1x = d1x * r1, v1y = d1y * r1, v1z = d1z * r1;

            float n2 = sqrtf(d2x * d2x + d2y * d2y + d2z * d2z) + 1e-10f;
            float r2 = 1.0f / n2;
            float v2x = d2x * r2, v2y = d2y * r2, v2z = d2z * r2;

            float dot = v1x * v2x + v1y * v2y + v1z * v2z;
            float cosang = fminf(1.0f, fmaxf(-1.0f, dot));
            float ang = acosf(cosang);

            float ux = v2x - dot * v1x;
            float uy = v2y - dot * v1y;
            float uz = v2z - dot * v1z;
            float nu = sqrtf(ux * ux + uy * uy + uz * uz) + 1e-10f;
            float ru = 1.0f / nu;
            float e2x = ux * ru, e2y = uy * ru, e2z = uz * ru;

            float e3x = v1y * e2z - v1z * e2y;
            float e3y = v1z * e2x - v1x * e2z;
            float e3z = v1x * e2y - v1y * e2x;

            s_ang[lrow] = (i == 0 || i == n - 1) ? 0.0f : ang;

            float* f = s_fr + 9 * lrow;
            f[0] = v1x; f[1] = v1y; f[2] = v1z;
            f[3] = e2x; f[4] = e2y; f[5] = e2z;
            f[6] = e3x; f[7] = e3y; f[8] = e3z;
        }
    }
    __syncthreads();

    // ---- Phase 3: vectorized store ----
    const int count = min(TILE, n - base);
    float* aptr = angles + 3 * (size_t)base;
    float* fptr = frames + 9 * (size_t)base;
    bool aligned16 = ((((uintptr_t)aptr) | ((uintptr_t)fptr)) & 15u) == 0;

    if (count == TILE && aligned16) {
        // angles: TILE*3 = 1536 floats = 384 float4
        float4* aout = (float4*)aptr;
        #pragma unroll
        for (int k = 0; k < 2; ++k) {
            int v = tid + k * THREADS;
            if (v < (TILE * 3) / 4) {
                int j = 4 * v;
                float4 w;
                w.x = s_ang[(j + 0) / 3];
                w.y = s_ang[(j + 1) / 3];
                w.z = s_ang[(j + 2) / 3];
                w.w = s_ang[(j + 3) / 3];
                aout[v] = w;
            }
        }
        // frames: TILE*9 = 4608 floats = 1152 float4
        float4* fout = (float4*)fptr;
        const float4* sf = (const float4*)s_fr;
        #pragma unroll
        for (int k = 0; k < 5; ++k) {
            int v = tid + k * THREADS;
            if (v < (TILE * 9) / 4) fout[v] = sf[v];
        }
    } else {
        for (int idx = tid; idx < count * 3; idx += THREADS)
            aptr[idx] = s_ang[idx / 3];
        for (int idx = tid; idx < count * 9; idx += THREADS)
            fptr[idx] = s_fr[idx];
    }
}

extern "C" void kernel_launch(void* const* d_in, const int* in_sizes, int n_in,
                              void* d_out, int out_size)
{
    const float* coords = (const float*)d_in[0];
    int n = in_sizes[0] / 3;

    float* angles = (float*)d_out;                  // (N,3)
    float* frames = (float*)d_out + 3 * (size_t)n;  // (N,3,3)

    int blocks = (n + TILE - 1) / TILE;
    geo_kernel<<<blocks, THREADS>>>(coords, angles, frames, n);
}

// round 8
// speedup vs baseline: 3.2824x; 1.0394x over previous
#include <cuda_runtime.h>
#include <math.h>
#include <stdint.h>

// GeometricFeatureExtractor: coords (N,3) f32 -> angles (N,3) + frames (N,3,3)
// Output layout: [angles (3N floats)][frames (9N floats)].
//
// 4 consecutive rows per thread. Interior blocks: direct LDG.128 input
// (aligned at 12*tid-4), shared normalizations across adjacent rows,
// vector STS staging, exact float4 copy-out. Edge blocks: scalar fallback.

#define THREADS 128
#define ROWS 4
#define TILE (THREADS * ROWS)   // 512

__device__ __forceinline__ void compute_row(
    float v1x, float v1y, float v1z,
    float v2x, float v2y, float v2z,
    float* __restrict__ fr9, float& ang)
{
    float dot = v1x * v2x + v1y * v2y + v1z * v2z;
    float cosang = fminf(1.0f, fmaxf(-1.0f, dot));
    ang = acosf(cosang);

    float ux = v2x - dot * v1x;
    float uy = v2y - dot * v1y;
    float uz = v2z - dot * v1z;
    float nu = sqrtf(ux * ux + uy * uy + uz * uz) + 1e-10f;
    float ru = __fdividef(1.0f, nu);
    float e2x = ux * ru, e2y = uy * ru, e2z = uz * ru;

    fr9[0] = v1x; fr9[1] = v1y; fr9[2] = v1z;
    fr9[3] = e2x; fr9[4] = e2y; fr9[5] = e2z;
    fr9[6] = v1y * e2z - v1z * e2y;
    fr9[7] = v1z * e2x - v1x * e2z;
    fr9[8] = v1x * e2y - v1y * e2x;
}

__global__ __launch_bounds__(THREADS) void geo_kernel(
    const float* __restrict__ coords,
    float* __restrict__ angles,
    float* __restrict__ frames,
    int n)
{
    __shared__ alignas(16) float s_ang3[TILE * 3];   // pre-expanded x3
    __shared__ alignas(16) float s_fr[TILE * 9];

    const int base = blockIdx.x * TILE;
    const int tid  = threadIdx.x;

    const bool interior = (base >= 1) && (base <= n - TILE - 2);

    if (interior) {
        // ---- load 6 coord rows (rows base+4*tid-1 .. +4) via 5 LDG.128 ----
        // float index 3*base + 12*tid - 4 is divisible by 4.
        alignas(16) float in[20];
        const float4* g4 = (const float4*)(coords + (3 * (size_t)base + 12 * tid - 4));
        #pragma unroll
        for (int j = 0; j < 5; ++j) ((float4*)in)[j] = g4[j];
        // coord row (base+4*tid-1+j) lives at in[3*j+1 .. 3*j+4), j=0..5

        // ---- 5 shared normalized difference vectors ----
        float vx[5], vy[5], vz[5];
        #pragma unroll
        for (int j = 0; j < 5; ++j) {
            float dx = in[3 * j + 4] - in[3 * j + 1];
            float dy = in[3 * j + 5] - in[3 * j + 2];
            float dz = in[3 * j + 6] - in[3 * j + 3];
            float nn = sqrtf(dx * dx + dy * dy + dz * dz) + 1e-10f;
            float r  = __fdividef(1.0f, nn);
            vx[j] = dx * r; vy[j] = dy * r; vz[j] = dz * r;
        }

        // ---- 4 rows: row k uses (v[k], v[k+1]) ----
        alignas(16) float fr[36];
        float a[4];
        #pragma unroll
        for (int k = 0; k < 4; ++k)
            compute_row(vx[k], vy[k], vz[k], vx[k + 1], vy[k + 1], vz[k + 1],
                        fr + 9 * k, a[k]);

        // ---- vector STS staging ----
        float4* sfr = (float4*)(s_fr + 36 * tid);
        #pragma unroll
        for (int q = 0; q < 9; ++q) sfr[q] = ((float4*)fr)[q];

        float4* sa = (float4*)(s_ang3 + 12 * tid);
        sa[0] = make_float4(a[0], a[0], a[0], a[1]);
        sa[1] = make_float4(a[1], a[1], a[2], a[2]);
        sa[2] = make_float4(a[2], a[3], a[3], a[3]);

        __syncthreads();

        // ---- exact float4 copy-out ----
        float4* fout = (float4*)(frames + 9 * (size_t)base);
        const float4* sf = (const float4*)s_fr;
        #pragma unroll
        for (int k = 0; k < 9; ++k) {
            int v = tid + k * THREADS;          // 9*128 = 1152 = TILE*9/4 exactly
            fout[v] = sf[v];
        }
        float4* aout = (float4*)(angles + 3 * (size_t)base);
        const float4* sa2 = (const float4*)s_ang3;
        #pragma unroll
        for (int k = 0; k < 3; ++k) {
            int v = tid + k * THREADS;          // 3*128 = 384 = TILE*3/4 exactly
            aout[v] = sa2[v];
        }
    } else {
        // ---- generic scalar path (first/last blocks only) ----
        for (int lr = tid; lr < TILE; lr += THREADS) {
            int i = base + lr;
            if (i >= n) break;
            int c = min(max(i, 1), n - 2);
            const float* p = coords + 3 * (size_t)(c - 1);
            float ax = p[0], ay = p[1], az = p[2];
            float bx = p[3], by = p[4], bz = p[5];
            float cx = p[6], cy = p[7], cz = p[8];

            float d1x = bx - ax, d1y = by - ay, d1z = bz - az;
            float d2x = cx - bx, d2y = cy - by, d2z = cz - bz;

            float n1 = sqrtf(d1x * d1x + d1y * d1y + d1z * d1z) + 1e-10f;
            float r1 = __fdividef(1.0f, n1);
            float v1x = d1x * r1, v1y = d1y * r1, v1z = d1z * r1;

            float n2 = sqrtf(d2x * d2x + d2y * d2y + d2z * d2z) + 1e-10f;
            float r2 = __fdividef(1.0f, n2);
            float v2x = d2x * r2, v2y = d2y * r2, v2z = d2z * r2;

            float fr9[9]; float ang;
            compute_row(v1x, v1y, v1z, v2x, v2y, v2z, fr9, ang);

            float aval = (i == 0 || i == n - 1) ? 0.0f : ang;
            float* ar = angles + 3 * (size_t)i;
            ar[0] = aval; ar[1] = aval; ar[2] = aval;
            float* f = frames + 9 * (size_t)i;
            #pragma unroll
            for (int q = 0; q < 9; ++q) f[q] = fr9[q];
        }
    }
}

extern "C" void kernel_launch(void* const* d_in, const int* in_sizes, int n_in,
                              void* d_out, int out_size)
{
    const float* coords = (const float*)d_in[0];
    int n = in_sizes[0] / 3;

    float* angles = (float*)d_out;                  // (N,3)
    float* frames = (float*)d_out + 3 * (size_t)n;  // (N,3,3)

    int blocks = (n + TILE - 1) / TILE;
    geo_kernel<<<blocks, THREADS>>>(coords, angles, frames, n);
}

// round 10
// speedup vs baseline: 3.3208x; 1.0117x over previous
#include <cuda_runtime.h>
#include <math.h>
#include <stdint.h>

// GeometricFeatureExtractor: coords (N,3) f32 -> angles (N,3) + frames (N,3,3)
// Output layout: [angles (3N floats)][frames (9N floats)].
//
// 4 consecutive rows per thread, per-warp 128-row sub-tiles with warp-local
// shared staging (__syncwarp only, no block barrier). Streaming cache hints
// on all global traffic. Edge blocks: scalar fallback.

#define THREADS 128
#define ROWS 4
#define WTILE 128               // rows per warp (32 lanes * 4 rows)
#define TILE (THREADS * ROWS)   // 512 rows per block

__device__ __forceinline__ void compute_row(
    float v1x, float v1y, float v1z,
    float v2x, float v2y, float v2z,
    float* __restrict__ fr9, float& ang)
{
    float dot = v1x * v2x + v1y * v2y + v1z * v2z;
    float cosang = fminf(1.0f, fmaxf(-1.0f, dot));
    ang = acosf(cosang);

    float ux = v2x - dot * v1x;
    float uy = v2y - dot * v1y;
    float uz = v2z - dot * v1z;
    float nu = sqrtf(ux * ux + uy * uy + uz * uz) + 1e-10f;
    float ru = __fdividef(1.0f, nu);
    float e2x = ux * ru, e2y = uy * ru, e2z = uz * ru;

    fr9[0] = v1x; fr9[1] = v1y; fr9[2] = v1z;
    fr9[3] = e2x; fr9[4] = e2y; fr9[5] = e2z;
    fr9[6] = v1y * e2z - v1z * e2y;
    fr9[7] = v1z * e2x - v1x * e2z;
    fr9[8] = v1x * e2y - v1y * e2x;
}

__global__ __launch_bounds__(THREADS) void geo_kernel(
    const float* __restrict__ coords,
    float* __restrict__ angles,
    float* __restrict__ frames,
    int n)
{
    __shared__ alignas(16) float s_fr[TILE * 9];   // 18432 B
    __shared__ alignas(16) float s_ang[TILE];      //  2048 B

    const int base = blockIdx.x * TILE;
    const int tid  = threadIdx.x;
    const int w    = tid >> 5;
    const int lane = tid & 31;

    const bool interior = (base >= 1) && (base <= n - TILE - 2);

    if (interior) {
        const int wbase = base + w * WTILE;

        // ---- load 6 coord rows (wbase+4*lane-1 .. +4) via 5 LDG.128 ----
        // float index 3*wbase + 12*lane - 4 is divisible by 4 (wbase % 4 == 0).
        alignas(16) float in[20];
        const float4* g4 = (const float4*)(coords + (3 * (size_t)wbase + 12 * lane - 4));
        #pragma unroll
        for (int j = 0; j < 5; ++j) ((float4*)in)[j] = __ldcs(g4 + j);

        // ---- 5 shared normalized difference vectors ----
        float vx[5], vy[5], vz[5];
        #pragma unroll
        for (int j = 0; j < 5; ++j) {
            float dx = in[3 * j + 4] - in[3 * j + 1];
            float dy = in[3 * j + 5] - in[3 * j + 2];
            float dz = in[3 * j + 6] - in[3 * j + 3];
            float nn = sqrtf(dx * dx + dy * dy + dz * dz) + 1e-10f;
            float r  = __fdividef(1.0f, nn);
            vx[j] = dx * r; vy[j] = dy * r; vz[j] = dz * r;
        }

        // ---- 4 rows: row k uses (v[k], v[k+1]) ----
        alignas(16) float fr[36];
        float a[4];
        #pragma unroll
        for (int k = 0; k < 4; ++k)
            compute_row(vx[k], vy[k], vz[k], vx[k + 1], vy[k + 1], vz[k + 1],
                        fr + 9 * k, a[k]);

        // ---- warp-local shared staging ----
        float* sfr_w  = s_fr + (size_t)w * WTILE * 9;
        float* sang_w = s_ang + w * WTILE;

        float4* sfr = (float4*)(sfr_w + 36 * lane);
        #pragma unroll
        for (int q = 0; q < 9; ++q) sfr[q] = ((float4*)fr)[q];
        ((float4*)(sang_w + 4 * lane))[0] = make_float4(a[0], a[1], a[2], a[3]);

        __syncwarp();

        // ---- coalesced streaming copy-out (warp covers its own 128 rows) ----
        float4* fout = (float4*)(frames + 9 * (size_t)wbase);
        const float4* sf = (const float4*)sfr_w;
        #pragma unroll
        for (int k = 0; k < 9; ++k) {           // 9*32 = 288 = WTILE*9/4 exactly
            int v = lane + 32 * k;
            __stcs(fout + v, sf[v]);
        }

        float4* aout = (float4*)(angles + 3 * (size_t)wbase);
        #pragma unroll
        for (int k = 0; k < 3; ++k) {           // 3*32 = 96 = WTILE*3/4 exactly
            int v = lane + 32 * k;
            int j = 4 * v;
            float4 av;
            av.x = sang_w[(j + 0) / 3];
            av.y = sang_w[(j + 1) / 3];
            av.z = sang_w[(j + 2) / 3];
            av.w = sang_w[(j + 3) / 3];
            __stcs(aout + v, av);
        }
    } else {
        // ---- generic scalar path (first/last blocks only) ----
        for (int lr = tid; lr < TILE; lr += THREADS) {
            int i = base + lr;
            if (i >= n) break;
            int c = min(max(i, 1), n - 2);
            const float* p = coords + 3 * (size_t)(c - 1);
            float ax = p[0], ay = p[1], az = p[2];
            float bx = p[3], by = p[4], bz = p[5];
            float cx = p[6], cy = p[7], cz = p[8];

            float d1x = bx - ax, d1y = by - ay, d1z = bz - az;
            float d2x = cx - bx, d2y = cy - by, d2z = cz - bz;

            float n1 = sqrtf(d1x * d1x + d1y * d1y + d1z * d1z) + 1e-10f;
            float r1 = __fdividef(1.0f, n1);
            float v1x = d1x * r1, v1y = d1y * r1, v1z = d1z * r1;

            float n2 = sqrtf(d2x * d2x + d2y * d2y + d2z * d2z) + 1e-10f;
            float r2 = __fdividef(1.0f, n2);
            float v2x = d2x * r2, v2y = d2y * r2, v2z = d2z * r2;

            float fr9[9]; float ang;
            compute_row(v1x, v1y, v1z, v2x, v2y, v2z, fr9, ang);

            float aval = (i == 0 || i == n - 1) ? 0.0f : ang;
            float* ar = angles + 3 * (size_t)i;
            ar[0] = aval; ar[1] = aval; ar[2] = aval;
            float* f = frames + 9 * (size_t)i;
            #pragma unroll
            for (int q = 0; q < 9; ++q) f[q] = fr9[q];
        }
    }
}

extern "C" void kernel_launch(void* const* d_in, const int* in_sizes, int n_in,
                              void* d_out, int out_size)
{
    const float* coords = (const float*)d_in[0];
    int n = in_sizes[0] / 3;

    float* angles = (float*)d_out;                  // (N,3)
    float* frames = (float*)d_out + 3 * (size_t)n;  // (N,3,3)

    int blocks = (n + TILE - 1) / TILE;
    geo_kernel<<<blocks, THREADS>>>(coords, angles, frames, n);
}